// round 16
// baseline (speedup 1.0000x reference)
#include <cuda_runtime.h>
#include <cuda_bf16.h>

#define NMAX 50000
#define EMAX 800000
#define ETOTMAX (EMAX + NMAX)

// Scratch (device globals: allocation-free; zero-initialized at module load)
__device__ float g_A[NMAX * 128];     // xl
__device__ float g_B[NMAX * 128];     // xr
__device__ float g_C[NMAX * 128];     // hidden
__device__ int   g_deg[NMAX];         // must be zero at call entry (re-zeroed in scan23)
__device__ int   g_row[NMAX + 1];
__device__ int   g_cursor[NMAX];
__device__ int   g_csr[ETOTMAX];      // src ids grouped by dst
__device__ int   g_bsum[256];         // per-block degree sums for scan

// ---------------------------------------------------------------------------
// helpers
// ---------------------------------------------------------------------------
__device__ __forceinline__ unsigned long long pack2(float lo, float hi) {
    unsigned long long r;
    asm("mov.b64 %0, {%1, %2};" : "=l"(r) : "f"(lo), "f"(hi));
    return r;
}
__device__ __forceinline__ void unpack2(unsigned long long v, float& lo, float& hi) {
    asm("mov.b64 {%0, %1}, %2;" : "=f"(lo), "=f"(hi) : "l"(v));
}
__device__ __forceinline__ void fma2(unsigned long long& d, unsigned long long a,
                                     unsigned long long b) {
    asm("fma.rn.f32x2 %0, %1, %2, %0;" : "+l"(d) : "l"(a), "l"(b));
}

// ---------------------------------------------------------------------------
// Dual GEMM: out = A @ W{0,1} + b{0,1}.  128x128 tile, 256 threads,
// 8x8 micro-tile (f32x2). W loaded ONCE per CTA into 64KB smem.
// ---------------------------------------------------------------------------
#define GD_SMEM (65536 + 16 * 132 * 4)

__global__ void __launch_bounds__(256, 2) gemm8_kernel(
    const float* __restrict__ A,
    const float* __restrict__ W0, const float* __restrict__ b0, float* __restrict__ out0,
    const float* __restrict__ W1, const float* __restrict__ b1, float* __restrict__ out1,
    int M)
{
    extern __shared__ float sm[];
    float* Wsm = sm;            // [128][128]
    float* At  = sm + 16384;    // [16][132]

    const float* W    = blockIdx.y ? W1 : W0;
    const float* bias = blockIdx.y ? b1 : b0;
    float*       out  = blockIdx.y ? out1 : out0;

    const int tid = threadIdx.x;
    const int m0  = blockIdx.x * 128;

    for (int i = tid; i < 4096; i += 256)
        ((float4*)Wsm)[i] = ((const float4*)W)[i];

    const int  r_ld   = tid >> 1;
    const int  q_ld   = tid & 1;
    const bool rvalid = (m0 + r_ld) < M;
    const float* aptr = A + (long long)(m0 + r_ld) * 128 + q_ld * 8;

    const int ty = tid >> 4;
    const int tx = tid & 15;

    unsigned long long acc[32];
#pragma unroll
    for (int i = 0; i < 32; i++) acc[i] = 0ull;

    float4 areg[2];
#pragma unroll
    for (int j = 0; j < 2; j++)
        areg[j] = rvalid ? *(const float4*)(aptr + j * 4) : make_float4(0.f, 0.f, 0.f, 0.f);

    for (int c = 0; c < 8; c++) {
        __syncthreads();
#pragma unroll
        for (int j = 0; j < 2; j++) {
            At[(q_ld * 8 + j * 4 + 0) * 132 + r_ld] = areg[j].x;
            At[(q_ld * 8 + j * 4 + 1) * 132 + r_ld] = areg[j].y;
            At[(q_ld * 8 + j * 4 + 2) * 132 + r_ld] = areg[j].z;
            At[(q_ld * 8 + j * 4 + 3) * 132 + r_ld] = areg[j].w;
        }
        __syncthreads();

        if (c < 7) {
#pragma unroll
            for (int j = 0; j < 2; j++)
                areg[j] = rvalid ? *(const float4*)(aptr + (c + 1) * 16 + j * 4)
                                 : make_float4(0.f, 0.f, 0.f, 0.f);
        }

#pragma unroll
        for (int k = 0; k < 16; k++) {
            const float4 a0 = *(const float4*)&At[k * 132 + ty * 8];
            const float4 a1 = *(const float4*)&At[k * 132 + ty * 8 + 4];
            const ulonglong2 wa = *(const ulonglong2*)&Wsm[(c * 16 + k) * 128 + tx * 8];
            const ulonglong2 wb = *(const ulonglong2*)&Wsm[(c * 16 + k) * 128 + tx * 8 + 4];
            const unsigned long long wv[4] = {wa.x, wa.y, wb.x, wb.y};
            const float as[8] = {a0.x, a0.y, a0.z, a0.w, a1.x, a1.y, a1.z, a1.w};
#pragma unroll
            for (int i = 0; i < 8; i++) {
                const unsigned long long ai = pack2(as[i], as[i]);
#pragma unroll
                for (int j = 0; j < 4; j++) fma2(acc[i * 4 + j], ai, wv[j]);
            }
        }
    }

    const int cbase = tx * 8;
    float4 bb0 = *(const float4*)&bias[cbase];
    float4 bb1 = *(const float4*)&bias[cbase + 4];
    const float bs[8] = {bb0.x, bb0.y, bb0.z, bb0.w, bb1.x, bb1.y, bb1.z, bb1.w};
#pragma unroll
    for (int i = 0; i < 8; i++) {
        const int row = m0 + ty * 8 + i;
        if (row < M) {
            float o[8];
#pragma unroll
            for (int j = 0; j < 4; j++) unpack2(acc[i * 4 + j], o[j * 2], o[j * 2 + 1]);
            float4 v0 = make_float4(o[0] + bs[0], o[1] + bs[1], o[2] + bs[2], o[3] + bs[3]);
            float4 v1 = make_float4(o[4] + bs[4], o[5] + bs[5], o[6] + bs[6], o[7] + bs[7]);
            *(float4*)&out[(long long)row * 128 + cbase]     = v0;
            *(float4*)&out[(long long)row * 128 + cbase + 4] = v1;
        }
    }
}

// ---------------------------------------------------------------------------
// CSR build: hist -> scan1 -> scan23 (+deg rezero) -> scatter
// ---------------------------------------------------------------------------
__global__ void __launch_bounds__(256) hist_kernel(const int* __restrict__ ei,
                                                   int* __restrict__ deg, int E, int Etot)
{
    int e = blockIdx.x * blockDim.x + threadIdx.x;
    if (e >= Etot) return;
    int d = (e < E) ? ei[E + e] : (e - E);
    atomicAdd(&deg[d], 1);
}

__global__ void __launch_bounds__(256) scan1_kernel(const int* __restrict__ deg,
                                                    int* __restrict__ bsum, int Nn)
{
    int i = blockIdx.x * 256 + threadIdx.x;
    int v = (i < Nn) ? deg[i] : 0;
#pragma unroll
    for (int off = 16; off; off >>= 1) v += __shfl_down_sync(0xffffffffu, v, off);
    __shared__ int ws[8];
    if ((threadIdx.x & 31) == 0) ws[threadIdx.x >> 5] = v;
    __syncthreads();
    if (threadIdx.x < 8) {
        int s = ws[threadIdx.x];
#pragma unroll
        for (int off = 4; off; off >>= 1) s += __shfl_down_sync(0xffu, s, off);
        if (threadIdx.x == 0) bsum[blockIdx.x] = s;
    }
}

__global__ void __launch_bounds__(256) scan23_kernel(int* __restrict__ deg,
                                                     const int* __restrict__ bsum,
                                                     int* __restrict__ row,
                                                     int* __restrict__ cursor,
                                                     int nb, int Nn, int Etot)
{
    const int t = threadIdx.x, lane = t & 31, w = t >> 5;
    const int bid = blockIdx.x;

    int pre = (t < nb && t < bid) ? bsum[t] : 0;
#pragma unroll
    for (int off = 16; off; off >>= 1) pre += __shfl_down_sync(0xffffffffu, pre, off);
    __shared__ int ws[8];
    if (lane == 0) ws[w] = pre;
    __syncthreads();
    if (t == 0) {
        int s = 0;
#pragma unroll
        for (int j = 0; j < 8; j++) s += ws[j];
        ws[0] = s;
    }
    __syncthreads();
    const int base = ws[0];
    __syncthreads();

    const int i = bid * 256 + t;
    const int v = (i < Nn) ? deg[i] : 0;
    int s = v;
#pragma unroll
    for (int off = 1; off < 32; off <<= 1) {
        int u = __shfl_up_sync(0xffffffffu, s, off);
        if (lane >= off) s += u;
    }
    __shared__ int wsum[8];
    if (lane == 31) wsum[w] = s;
    __syncthreads();
    if (t < 8) {
        int x = wsum[t], y = x;
#pragma unroll
        for (int off = 1; off < 8; off <<= 1) {
            int u = __shfl_up_sync(0xffu, y, off);
            if (t >= off) y += u;
        }
        wsum[t] = y - x;
    }
    __syncthreads();
    const int excl = s - v + wsum[w] + base;
    if (i < Nn) {
        row[i]    = excl;
        cursor[i] = excl;
        deg[i]    = 0;
    }
    if (i == 0) row[Nn] = Etot;
}

__global__ void __launch_bounds__(256) scatter_kernel(const int* __restrict__ ei,
                                                      int* __restrict__ cursor,
                                                      int* __restrict__ csr, int E, int Etot)
{
    int e = blockIdx.x * blockDim.x + threadIdx.x;
    if (e >= Etot) return;
    int s, d;
    if (e < E) { s = ei[e]; d = ei[E + e]; }
    else       { s = e - E; d = s; }
    int pos = atomicAdd(&cursor[d], 1);
    csr[pos] = s;
}

// ---------------------------------------------------------------------------
// Node-parallel fused GATv2 aggregation: grid-stride, ~8 nodes per warp
// (averages Poisson degree variance; cuts block-retirement idle waste).
// ---------------------------------------------------------------------------
__device__ __forceinline__ float lrelu(float x) { return fmaxf(x, 0.2f * x); }

template<int H, bool RELU>
__global__ void __launch_bounds__(256) node_agg_kernel(
    const float* __restrict__ xl, const float* __restrict__ xr,
    const int* __restrict__ row, const int* __restrict__ csr,
    const float* __restrict__ att, const float* __restrict__ bias,
    float* __restrict__ out, int Nn)
{
    const int lane   = threadIdx.x & 31;
    const int warp0  = (blockIdx.x * blockDim.x + threadIdx.x) >> 5;
    const int nwarps = (gridDim.x * blockDim.x) >> 5;

    const float4 at = ((const float4*)att)[lane];
    const float4 bb = ((const float4*)bias)[lane];

    for (int n = warp0; n < Nn; n += nwarps) {
        const float4 b = ((const float4*)xr)[n * 32 + lane];

        const int beg = row[n];
        const int end = row[n + 1];

        float4 acc = make_float4(0.f, 0.f, 0.f, 0.f);
        float  den = 0.f;

        float4 a = ((const float4*)xl)[csr[beg] * 32 + lane];
        for (int i = beg; i < end; i++) {
            float4 ac = a;
            if (i + 1 < end) a = ((const float4*)xl)[csr[i + 1] * 32 + lane];

            float p = lrelu(ac.x + b.x) * at.x;
            p = fmaf(lrelu(ac.y + b.y), at.y, p);
            p = fmaf(lrelu(ac.z + b.z), at.z, p);
            p = fmaf(lrelu(ac.w + b.w), at.w, p);
            p += __shfl_xor_sync(0xffffffffu, p, 1);
            p += __shfl_xor_sync(0xffffffffu, p, 2);
            p += __shfl_xor_sync(0xffffffffu, p, 4);
            if (H == 1) {
                p += __shfl_xor_sync(0xffffffffu, p, 8);
                p += __shfl_xor_sync(0xffffffffu, p, 16);
            }
            float ex = __expf(p);
            den  += ex;
            acc.x = fmaf(ac.x, ex, acc.x);
            acc.y = fmaf(ac.y, ex, acc.y);
            acc.z = fmaf(ac.z, ex, acc.z);
            acc.w = fmaf(ac.w, ex, acc.w);
        }

        const float r = 1.0f / (den + 1e-16f);
        float4 v;
        v.x = fmaf(acc.x, r, bb.x);
        v.y = fmaf(acc.y, r, bb.y);
        v.z = fmaf(acc.z, r, bb.z);
        v.w = fmaf(acc.w, r, bb.w);
        if (RELU) {
            v.x = fmaxf(v.x, 0.f); v.y = fmaxf(v.y, 0.f);
            v.z = fmaxf(v.z, 0.f); v.w = fmaxf(v.w, 0.f);
        }
        ((float4*)out)[n * 32 + lane] = v;
    }
}

// ---------------------------------------------------------------------------
// launch — R12 schedule: CSR chain forked under gemm1; serial layer path.
// ---------------------------------------------------------------------------
extern "C" void kernel_launch(void* const* d_in, const int* in_sizes, int n_in,
                              void* d_out, int out_size)
{
    const int*   ei    = (const int*)d_in[0];
    const float* embed = (const float*)d_in[1];
    const float* Wl1   = (const float*)d_in[2];
    const float* bl1   = (const float*)d_in[3];
    const float* Wr1   = (const float*)d_in[4];
    const float* br1   = (const float*)d_in[5];
    const float* att1  = (const float*)d_in[6];
    const float* b1    = (const float*)d_in[7];
    const float* Wl2   = (const float*)d_in[8];
    const float* bl2   = (const float*)d_in[9];
    const float* Wr2   = (const float*)d_in[10];
    const float* br2   = (const float*)d_in[11];
    const float* att2  = (const float*)d_in[12];
    const float* b2    = (const float*)d_in[13];
    float* out = (float*)d_out;

    const int E    = in_sizes[0] / 2;
    const int Nn   = in_sizes[1] / 128;
    const int Etot = E + Nn;

    float *A, *B, *C;
    int *deg, *row, *cursor, *csr, *bsum;
    cudaGetSymbolAddress((void**)&A,      g_A);
    cudaGetSymbolAddress((void**)&B,      g_B);
    cudaGetSymbolAddress((void**)&C,      g_C);
    cudaGetSymbolAddress((void**)&deg,    g_deg);
    cudaGetSymbolAddress((void**)&row,    g_row);
    cudaGetSymbolAddress((void**)&cursor, g_cursor);
    cudaGetSymbolAddress((void**)&csr,    g_csr);
    cudaGetSymbolAddress((void**)&bsum,   g_bsum);

    static cudaStream_t s_side = nullptr;
    static cudaEvent_t  ev_fork = nullptr, ev_csr = nullptr;
    if (s_side == nullptr) {
        cudaStreamCreateWithFlags(&s_side, cudaStreamNonBlocking);
        cudaEventCreateWithFlags(&ev_fork, cudaEventDisableTiming);
        cudaEventCreateWithFlags(&ev_csr,  cudaEventDisableTiming);
        cudaFuncSetAttribute(gemm8_kernel,
                             cudaFuncAttributeMaxDynamicSharedMemorySize, GD_SMEM);
    }

    const dim3 gemm_grid((Nn + 127) / 128, 2);
    const int  ethr_blocks  = (Etot + 255) / 256;
    const int  agg_blocks   = (Nn + 63) / 64;     // 8 warps/block, ~8 nodes/warp
    const int  nscan_blocks = (Nn + 255) / 256;   // 196 <= 256

    // ---- fork: CSR chain on side stream, gemm1 on main ----
    cudaEventRecord(ev_fork, 0);
    cudaStreamWaitEvent(s_side, ev_fork, 0);

    hist_kernel<<<ethr_blocks, 256, 0, s_side>>>(ei, deg, E, Etot);
    scan1_kernel<<<nscan_blocks, 256, 0, s_side>>>(deg, bsum, Nn);
    scan23_kernel<<<nscan_blocks, 256, 0, s_side>>>(deg, bsum, row, cursor,
                                                    nscan_blocks, Nn, Etot);
    scatter_kernel<<<ethr_blocks, 256, 0, s_side>>>(ei, cursor, csr, E, Etot);
    cudaEventRecord(ev_csr, s_side);

    gemm8_kernel<<<gemm_grid, 256, GD_SMEM>>>(embed, Wl1, bl1, A, Wr1, br1, B, Nn);

    // ---- join CSR before agg1 ----
    cudaStreamWaitEvent(0, ev_csr, 0);

    // ---- layer 1 aggregation, then layer 2 ----
    node_agg_kernel<4, true><<<agg_blocks, 256>>>(A, B, row, csr, att1, b1, C, Nn);
    gemm8_kernel<<<gemm_grid, 256, GD_SMEM>>>(C, Wl2, bl2, A, Wr2, br2, B, Nn);
    node_agg_kernel<1, false><<<agg_blocks, 256>>>(A, B, row, csr, att2, b2, out, Nn);
}

// round 17
// speedup vs baseline: 1.1502x; 1.1502x over previous
#include <cuda_runtime.h>
#include <cuda_bf16.h>

#define NMAX 50000
#define EMAX 800000
#define ETOTMAX (EMAX + NMAX)

// Scratch (device globals: allocation-free; zero-initialized at module load)
__device__ float g_A[NMAX * 128];     // xl
__device__ float g_B[NMAX * 128];     // xr
__device__ float g_C[NMAX * 128];     // hidden
__device__ int   g_deg[NMAX];         // must be zero at call entry (re-zeroed in scan23)
__device__ int   g_row[NMAX + 1];
__device__ int   g_cursor[NMAX];
__device__ int   g_csr[ETOTMAX];      // src ids grouped by dst
__device__ int   g_bsum[256];         // per-block degree sums for scan

// ---------------------------------------------------------------------------
// helpers
// ---------------------------------------------------------------------------
__device__ __forceinline__ unsigned long long pack2(float lo, float hi) {
    unsigned long long r;
    asm("mov.b64 %0, {%1, %2};" : "=l"(r) : "f"(lo), "f"(hi));
    return r;
}
__device__ __forceinline__ void unpack2(unsigned long long v, float& lo, float& hi) {
    asm("mov.b64 {%0, %1}, %2;" : "=f"(lo), "=f"(hi) : "l"(v));
}
__device__ __forceinline__ void fma2(unsigned long long& d, unsigned long long a,
                                     unsigned long long b) {
    asm("fma.rn.f32x2 %0, %1, %2, %0;" : "+l"(d) : "l"(a), "l"(b));
}

// ---------------------------------------------------------------------------
// Dual GEMM: out = A @ W{0,1} + b{0,1}.  128x128 tile, 256 threads,
// 8x8 micro-tile (f32x2). W loaded ONCE per CTA into 64KB smem.
// ---------------------------------------------------------------------------
#define GD_SMEM (65536 + 16 * 132 * 4)

__global__ void __launch_bounds__(256, 2) gemm8_kernel(
    const float* __restrict__ A,
    const float* __restrict__ W0, const float* __restrict__ b0, float* __restrict__ out0,
    const float* __restrict__ W1, const float* __restrict__ b1, float* __restrict__ out1,
    int M)
{
    extern __shared__ float sm[];
    float* Wsm = sm;            // [128][128]
    float* At  = sm + 16384;    // [16][132]

    const float* W    = blockIdx.y ? W1 : W0;
    const float* bias = blockIdx.y ? b1 : b0;
    float*       out  = blockIdx.y ? out1 : out0;

    const int tid = threadIdx.x;
    const int m0  = blockIdx.x * 128;

    for (int i = tid; i < 4096; i += 256)
        ((float4*)Wsm)[i] = ((const float4*)W)[i];

    const int  r_ld   = tid >> 1;
    const int  q_ld   = tid & 1;
    const bool rvalid = (m0 + r_ld) < M;
    const float* aptr = A + (long long)(m0 + r_ld) * 128 + q_ld * 8;

    const int ty = tid >> 4;
    const int tx = tid & 15;

    unsigned long long acc[32];
#pragma unroll
    for (int i = 0; i < 32; i++) acc[i] = 0ull;

    float4 areg[2];
#pragma unroll
    for (int j = 0; j < 2; j++)
        areg[j] = rvalid ? *(const float4*)(aptr + j * 4) : make_float4(0.f, 0.f, 0.f, 0.f);

    for (int c = 0; c < 8; c++) {
        __syncthreads();
#pragma unroll
        for (int j = 0; j < 2; j++) {
            At[(q_ld * 8 + j * 4 + 0) * 132 + r_ld] = areg[j].x;
            At[(q_ld * 8 + j * 4 + 1) * 132 + r_ld] = areg[j].y;
            At[(q_ld * 8 + j * 4 + 2) * 132 + r_ld] = areg[j].z;
            At[(q_ld * 8 + j * 4 + 3) * 132 + r_ld] = areg[j].w;
        }
        __syncthreads();

        if (c < 7) {
#pragma unroll
            for (int j = 0; j < 2; j++)
                areg[j] = rvalid ? *(const float4*)(aptr + (c + 1) * 16 + j * 4)
                                 : make_float4(0.f, 0.f, 0.f, 0.f);
        }

#pragma unroll
        for (int k = 0; k < 16; k++) {
            const float4 a0 = *(const float4*)&At[k * 132 + ty * 8];
            const float4 a1 = *(const float4*)&At[k * 132 + ty * 8 + 4];
            const ulonglong2 wa = *(const ulonglong2*)&Wsm[(c * 16 + k) * 128 + tx * 8];
            const ulonglong2 wb = *(const ulonglong2*)&Wsm[(c * 16 + k) * 128 + tx * 8 + 4];
            const unsigned long long wv[4] = {wa.x, wa.y, wb.x, wb.y};
            const float as[8] = {a0.x, a0.y, a0.z, a0.w, a1.x, a1.y, a1.z, a1.w};
#pragma unroll
            for (int i = 0; i < 8; i++) {
                const unsigned long long ai = pack2(as[i], as[i]);
#pragma unroll
                for (int j = 0; j < 4; j++) fma2(acc[i * 4 + j], ai, wv[j]);
            }
        }
    }

    const int cbase = tx * 8;
    float4 bb0 = *(const float4*)&bias[cbase];
    float4 bb1 = *(const float4*)&bias[cbase + 4];
    const float bs[8] = {bb0.x, bb0.y, bb0.z, bb0.w, bb1.x, bb1.y, bb1.z, bb1.w};
#pragma unroll
    for (int i = 0; i < 8; i++) {
        const int row = m0 + ty * 8 + i;
        if (row < M) {
            float o[8];
#pragma unroll
            for (int j = 0; j < 4; j++) unpack2(acc[i * 4 + j], o[j * 2], o[j * 2 + 1]);
            float4 v0 = make_float4(o[0] + bs[0], o[1] + bs[1], o[2] + bs[2], o[3] + bs[3]);
            float4 v1 = make_float4(o[4] + bs[4], o[5] + bs[5], o[6] + bs[6], o[7] + bs[7]);
            *(float4*)&out[(long long)row * 128 + cbase]     = v0;
            *(float4*)&out[(long long)row * 128 + cbase + 4] = v1;
        }
    }
}

// ---------------------------------------------------------------------------
// CSR build: hist -> scan1 -> scan23 (+deg rezero) -> scatter
// ---------------------------------------------------------------------------
__global__ void __launch_bounds__(256) hist_kernel(const int* __restrict__ ei,
                                                   int* __restrict__ deg, int E, int Etot)
{
    int e = blockIdx.x * blockDim.x + threadIdx.x;
    if (e >= Etot) return;
    int d = (e < E) ? ei[E + e] : (e - E);
    atomicAdd(&deg[d], 1);
}

__global__ void __launch_bounds__(256) scan1_kernel(const int* __restrict__ deg,
                                                    int* __restrict__ bsum, int Nn)
{
    int i = blockIdx.x * 256 + threadIdx.x;
    int v = (i < Nn) ? deg[i] : 0;
#pragma unroll
    for (int off = 16; off; off >>= 1) v += __shfl_down_sync(0xffffffffu, v, off);
    __shared__ int ws[8];
    if ((threadIdx.x & 31) == 0) ws[threadIdx.x >> 5] = v;
    __syncthreads();
    if (threadIdx.x < 8) {
        int s = ws[threadIdx.x];
#pragma unroll
        for (int off = 4; off; off >>= 1) s += __shfl_down_sync(0xffu, s, off);
        if (threadIdx.x == 0) bsum[blockIdx.x] = s;
    }
}

__global__ void __launch_bounds__(256) scan23_kernel(int* __restrict__ deg,
                                                     const int* __restrict__ bsum,
                                                     int* __restrict__ row,
                                                     int* __restrict__ cursor,
                                                     int nb, int Nn, int Etot)
{
    const int t = threadIdx.x, lane = t & 31, w = t >> 5;
    const int bid = blockIdx.x;

    int pre = (t < nb && t < bid) ? bsum[t] : 0;
#pragma unroll
    for (int off = 16; off; off >>= 1) pre += __shfl_down_sync(0xffffffffu, pre, off);
    __shared__ int ws[8];
    if (lane == 0) ws[w] = pre;
    __syncthreads();
    if (t == 0) {
        int s = 0;
#pragma unroll
        for (int j = 0; j < 8; j++) s += ws[j];
        ws[0] = s;
    }
    __syncthreads();
    const int base = ws[0];
    __syncthreads();

    const int i = bid * 256 + t;
    const int v = (i < Nn) ? deg[i] : 0;
    int s = v;
#pragma unroll
    for (int off = 1; off < 32; off <<= 1) {
        int u = __shfl_up_sync(0xffffffffu, s, off);
        if (lane >= off) s += u;
    }
    __shared__ int wsum[8];
    if (lane == 31) wsum[w] = s;
    __syncthreads();
    if (t < 8) {
        int x = wsum[t], y = x;
#pragma unroll
        for (int off = 1; off < 8; off <<= 1) {
            int u = __shfl_up_sync(0xffu, y, off);
            if (t >= off) y += u;
        }
        wsum[t] = y - x;
    }
    __syncthreads();
    const int excl = s - v + wsum[w] + base;
    if (i < Nn) {
        row[i]    = excl;
        cursor[i] = excl;
        deg[i]    = 0;
    }
    if (i == 0) row[Nn] = Etot;
}

__global__ void __launch_bounds__(256) scatter_kernel(const int* __restrict__ ei,
                                                      int* __restrict__ cursor,
                                                      int* __restrict__ csr, int E, int Etot)
{
    int e = blockIdx.x * blockDim.x + threadIdx.x;
    if (e >= Etot) return;
    int s, d;
    if (e < E) { s = ei[e]; d = ei[E + e]; }
    else       { s = e - E; d = s; }
    int pos = atomicAdd(&cursor[d], 1);
    csr[pos] = s;
}

// ---------------------------------------------------------------------------
// Node-parallel fused GATv2 aggregation: one warp per dst node (R12 version).
// 128-thread blocks: finer block-retirement granularity than 256.
// ---------------------------------------------------------------------------
__device__ __forceinline__ float lrelu(float x) { return fmaxf(x, 0.2f * x); }

template<int H, bool RELU>
__global__ void __launch_bounds__(128) node_agg_kernel(
    const float* __restrict__ xl, const float* __restrict__ xr,
    const int* __restrict__ row, const int* __restrict__ csr,
    const float* __restrict__ att, const float* __restrict__ bias,
    float* __restrict__ out, int Nn)
{
    int n = (blockIdx.x * blockDim.x + threadIdx.x) >> 5;
    if (n >= Nn) return;
    const int lane = threadIdx.x & 31;

    const float4 b  = ((const float4*)xr)[n * 32 + lane];
    const float4 at = ((const float4*)att)[lane];

    const int beg = row[n];
    const int end = row[n + 1];

    float4 acc = make_float4(0.f, 0.f, 0.f, 0.f);
    float  den = 0.f;

    float4 a = ((const float4*)xl)[csr[beg] * 32 + lane];
    for (int i = beg; i < end; i++) {
        float4 ac = a;
        if (i + 1 < end) a = ((const float4*)xl)[csr[i + 1] * 32 + lane];

        float p = lrelu(ac.x + b.x) * at.x;
        p = fmaf(lrelu(ac.y + b.y), at.y, p);
        p = fmaf(lrelu(ac.z + b.z), at.z, p);
        p = fmaf(lrelu(ac.w + b.w), at.w, p);
        p += __shfl_xor_sync(0xffffffffu, p, 1);
        p += __shfl_xor_sync(0xffffffffu, p, 2);
        p += __shfl_xor_sync(0xffffffffu, p, 4);
        if (H == 1) {
            p += __shfl_xor_sync(0xffffffffu, p, 8);
            p += __shfl_xor_sync(0xffffffffu, p, 16);
        }
        float ex = __expf(p);
        den  += ex;
        acc.x = fmaf(ac.x, ex, acc.x);
        acc.y = fmaf(ac.y, ex, acc.y);
        acc.z = fmaf(ac.z, ex, acc.z);
        acc.w = fmaf(ac.w, ex, acc.w);
    }

    const float r  = 1.0f / (den + 1e-16f);
    const float4 bb = ((const float4*)bias)[lane];
    float4 v;
    v.x = fmaf(acc.x, r, bb.x);
    v.y = fmaf(acc.y, r, bb.y);
    v.z = fmaf(acc.z, r, bb.z);
    v.w = fmaf(acc.w, r, bb.w);
    if (RELU) {
        v.x = fmaxf(v.x, 0.f); v.y = fmaxf(v.y, 0.f);
        v.z = fmaxf(v.z, 0.f); v.w = fmaxf(v.w, 0.f);
    }
    ((float4*)out)[n * 32 + lane] = v;
}

// ---------------------------------------------------------------------------
// launch — R12 schedule: CSR chain forked under gemm1; serial layer path.
// ---------------------------------------------------------------------------
extern "C" void kernel_launch(void* const* d_in, const int* in_sizes, int n_in,
                              void* d_out, int out_size)
{
    const int*   ei    = (const int*)d_in[0];
    const float* embed = (const float*)d_in[1];
    const float* Wl1   = (const float*)d_in[2];
    const float* bl1   = (const float*)d_in[3];
    const float* Wr1   = (const float*)d_in[4];
    const float* br1   = (const float*)d_in[5];
    const float* att1  = (const float*)d_in[6];
    const float* b1    = (const float*)d_in[7];
    const float* Wl2   = (const float*)d_in[8];
    const float* bl2   = (const float*)d_in[9];
    const float* Wr2   = (const float*)d_in[10];
    const float* br2   = (const float*)d_in[11];
    const float* att2  = (const float*)d_in[12];
    const float* b2    = (const float*)d_in[13];
    float* out = (float*)d_out;

    const int E    = in_sizes[0] / 2;
    const int Nn   = in_sizes[1] / 128;
    const int Etot = E + Nn;

    float *A, *B, *C;
    int *deg, *row, *cursor, *csr, *bsum;
    cudaGetSymbolAddress((void**)&A,      g_A);
    cudaGetSymbolAddress((void**)&B,      g_B);
    cudaGetSymbolAddress((void**)&C,      g_C);
    cudaGetSymbolAddress((void**)&deg,    g_deg);
    cudaGetSymbolAddress((void**)&row,    g_row);
    cudaGetSymbolAddress((void**)&cursor, g_cursor);
    cudaGetSymbolAddress((void**)&csr,    g_csr);
    cudaGetSymbolAddress((void**)&bsum,   g_bsum);

    static cudaStream_t s_side = nullptr;
    static cudaEvent_t  ev_fork = nullptr, ev_csr = nullptr;
    if (s_side == nullptr) {
        cudaStreamCreateWithFlags(&s_side, cudaStreamNonBlocking);
        cudaEventCreateWithFlags(&ev_fork, cudaEventDisableTiming);
        cudaEventCreateWithFlags(&ev_csr,  cudaEventDisableTiming);
        cudaFuncSetAttribute(gemm8_kernel,
                             cudaFuncAttributeMaxDynamicSharedMemorySize, GD_SMEM);
    }

    const dim3 gemm_grid((Nn + 127) / 128, 2);
    const int  ethr_blocks  = (Etot + 255) / 256;
    const int  nwarp_blocks = (Nn * 4 + 3) / 4;          // warp-per-node, 4 warps/block
    const int  agg_blocks   = (Nn + 3) / 4;              // 128 threads = 4 warps
    const int  nscan_blocks = (Nn + 255) / 256;          // 196 <= 256
    (void)nwarp_blocks;

    // ---- fork: CSR chain on side stream, gemm1 on main ----
    cudaEventRecord(ev_fork, 0);
    cudaStreamWaitEvent(s_side, ev_fork, 0);

    hist_kernel<<<ethr_blocks, 256, 0, s_side>>>(ei, deg, E, Etot);
    scan1_kernel<<<nscan_blocks, 256, 0, s_side>>>(deg, bsum, Nn);
    scan23_kernel<<<nscan_blocks, 256, 0, s_side>>>(deg, bsum, row, cursor,
                                                    nscan_blocks, Nn, Etot);
    scatter_kernel<<<ethr_blocks, 256, 0, s_side>>>(ei, cursor, csr, E, Etot);
    cudaEventRecord(ev_csr, s_side);

    gemm8_kernel<<<gemm_grid, 256, GD_SMEM>>>(embed, Wl1, bl1, A, Wr1, br1, B, Nn);

    // ---- join CSR before agg1 ----
    cudaStreamWaitEvent(0, ev_csr, 0);

    // ---- layer 1 aggregation, then layer 2 ----
    node_agg_kernel<4, true><<<agg_blocks, 128>>>(A, B, row, csr, att1, b1, C, Nn);
    gemm8_kernel<<<gemm_grid, 256, GD_SMEM>>>(C, Wl2, bl2, A, Wr2, br2, B, Nn);
    node_agg_kernel<1, false><<<agg_blocks, 128>>>(A, B, row, csr, att2, b2, out, Nn);
}